// round 13
// baseline (speedup 1.0000x reference)
#include <cuda_runtime.h>
#include <cuda_fp16.h>
#include <math.h>
#include <stdint.h>

// Problem constants
#define BB 2
#define TT 2048
#define DD 1024
#define HH 16
#define DH 64
#define FFN 4096
#define MROWS (BB*TT)          // 4096
#define LN_EPS 1e-3f

// FP16 GEMM tiling: 128x128x32 block, 128 threads (4 warps), warp tile 64x64
#define BM 128
#define BN 128
#define BKK 32                  // k-halves per stage
#define ASH 40                  // A smem row stride (halves)
#define BSH 40
#define STAGE_HALVES (BM*ASH + BN*BSH)      // 10240
#define GEMM_SMEM (2*STAGE_HALVES*2)        // 40960 bytes

// Flash tiling (fp16 operands)
#define QSH 72                  // [q][d] halves
#define KSH 72                  // [t][d] halves (K natural layout)
#define VSH 72                  // [t][d] halves
#define PSH 72                  // [q][kk] halves (P)
#define SFS 68                  // [q][kk] floats (S scores)
#define FL_SMEM_BYTES (64*QSH*2 + 2*64*KSH*2 + 2*64*VSH*2 + 64*SFS*4 + 64*PSH*2 + 4*64*4)

// ---------------------------------------------------------------------------
// Scratch (device globals; no allocation allowed)
// ---------------------------------------------------------------------------
__device__ __half g_xn_h [MROWS*DD];
__device__ __half g_q_h  [MROWS*DD];
__device__ __half g_k_h  [MROWS*DD];
__device__ __half g_v_h  [MROWS*DD];
__device__ __half g_h1n_h[MROWS*DD];
__device__ __half g_ff_h [MROWS*FFN];
__device__ float  g_res1 [MROWS*DD];
__device__ float  g_res2 [MROWS*DD];
// fp16 TRANSPOSED weight copies w[n][k]
__device__ __half g_wq_h[DD*DD];
__device__ __half g_wk_h[DD*DD];
__device__ __half g_wv_h[DD*DD];
__device__ __half g_w1_h[FFN*DD];
__device__ __half g_w2_h[DD*FFN];

// ---------------------------------------------------------------------------
// Helpers
// ---------------------------------------------------------------------------
__device__ __forceinline__ void cp16(void* dst, const void* src) {
    unsigned s = (unsigned)__cvta_generic_to_shared(dst);
    asm volatile("cp.async.cg.shared.global [%0], [%1], 16;" :: "r"(s), "l"(src));
}

__device__ __forceinline__ unsigned smem_addr(const void* p) {
    return (unsigned)__cvta_generic_to_shared(p);
}

#define MMA_F16(c, a, b) \
    asm volatile("mma.sync.aligned.m16n8k16.row.col.f32.f16.f16.f32 " \
        "{%0,%1,%2,%3}, {%4,%5,%6,%7}, {%8,%9}, {%0,%1,%2,%3};" \
        : "+f"((c)[0]), "+f"((c)[1]), "+f"((c)[2]), "+f"((c)[3]) \
        : "r"((a)[0]), "r"((a)[1]), "r"((a)[2]), "r"((a)[3]), \
          "r"((b)[0]), "r"((b)[1]))

#define LDSM_X4(r0, r1, r2, r3, addr) \
    asm volatile("ldmatrix.sync.aligned.m8n8.x4.shared.b16 {%0,%1,%2,%3}, [%4];" \
        : "=r"(r0), "=r"(r1), "=r"(r2), "=r"(r3) : "r"(addr))

#define LDSM_X4_T(r0, r1, r2, r3, addr) \
    asm volatile("ldmatrix.sync.aligned.m8n8.x4.trans.shared.b16 {%0,%1,%2,%3}, [%4];" \
        : "=r"(r0), "=r"(r1), "=r"(r2), "=r"(r3) : "r"(addr))

// two fp16 exponentials (base-2) in ONE MUFU op
__device__ __forceinline__ unsigned ex2_f16x2(unsigned y) {
    unsigned r;
    asm("ex2.approx.f16x2 %0, %1;" : "=r"(r) : "r"(y));
    return r;
}

// ---------------------------------------------------------------------------
// Weight -> fp16 (rn) + transpose: in[K][N] fp32 -> out[N][K] half
// ---------------------------------------------------------------------------
struct CvtTJobs {
    const float* in[3];
    __half* out[3];
};

__global__ void cvt_half_T_kernel(CvtTJobs j, int K, int N) {
    __shared__ float tile[32][33];
    int z = blockIdx.z;
    if (!j.in[z]) return;
    const float* in = j.in[z];
    __half* outp = j.out[z];
    int n0 = blockIdx.x * 32, k0 = blockIdx.y * 32;
    int tx = threadIdx.x, ty = threadIdx.y;   // 32 x 8
#pragma unroll
    for (int i = 0; i < 4; i++)
        tile[ty + 8 * i][tx] = in[(size_t)(k0 + ty + 8 * i) * N + n0 + tx];
    __syncthreads();
#pragma unroll
    for (int i = 0; i < 4; i++)
        outp[(size_t)(n0 + ty + 8 * i) * K + k0 + tx] =
            __float2half_rn(tile[tx][ty + 8 * i]);
}

// ---------------------------------------------------------------------------
// LayerNorm over last dim (D=1024); writes fp32 OR fp16 output
// ---------------------------------------------------------------------------
__device__ __forceinline__ float block_reduce_sum_256(float v, float* red) {
    __syncthreads();
#pragma unroll
    for (int o = 16; o > 0; o >>= 1) v += __shfl_xor_sync(0xffffffffu, v, o);
    int lane = threadIdx.x & 31, wid = threadIdx.x >> 5;
    if (lane == 0) red[wid] = v;
    __syncthreads();
    if (wid == 0) {
        v = (lane < 8) ? red[lane] : 0.f;
#pragma unroll
        for (int o = 4; o > 0; o >>= 1) v += __shfl_xor_sync(0xffffffffu, v, o);
        if (lane == 0) red[0] = v;
    }
    __syncthreads();
    return red[0];
}

__global__ void ln1024_kernel(const float* __restrict__ x,
                              const float* __restrict__ gamma,
                              const float* __restrict__ beta,
                              float* __restrict__ outf,
                              __half* __restrict__ outh) {
    __shared__ float red[8];
    int row = blockIdx.x;
    int t = threadIdx.x;
    const float4 v = reinterpret_cast<const float4*>(x + (size_t)row * DD)[t];

    float s = v.x + v.y + v.z + v.w;
    float mu = block_reduce_sum_256(s, red) * (1.0f / DD);

    float dx = v.x - mu, dy = v.y - mu, dz = v.z - mu, dw = v.w - mu;
    float q = dx*dx + dy*dy + dz*dz + dw*dw;
    float var = block_reduce_sum_256(q, red) * (1.0f / DD);
    float r = rsqrtf(var + LN_EPS);

    const float4 gg = reinterpret_cast<const float4*>(gamma)[t];
    const float4 bb = reinterpret_cast<const float4*>(beta)[t];
    float o0 = dx * r * gg.x + bb.x;
    float o1 = dy * r * gg.y + bb.y;
    float o2 = dz * r * gg.z + bb.z;
    float o3 = dw * r * gg.w + bb.w;
    if (outh) {
        __half2 h0 = __floats2half2_rn(o0, o1);
        __half2 h1 = __floats2half2_rn(o2, o3);
        reinterpret_cast<__half2*>(outh + (size_t)row * DD)[2 * t] = h0;
        reinterpret_cast<__half2*>(outh + (size_t)row * DD)[2 * t + 1] = h1;
    } else {
        float4 o = {o0, o1, o2, o3};
        reinterpret_cast<float4*>(outf + (size_t)row * DD)[t] = o;
    }
}

// ---------------------------------------------------------------------------
// FP16 tensor-core GEMM (unchanged from round 12)
// ---------------------------------------------------------------------------
__device__ __forceinline__ void gemm_prefetch(const __half* __restrict__ A,
                                              const __half* __restrict__ Bt,
                                              int K, int bm0, int bn0,
                                              int kt, __half* As, __half* Bs,
                                              int tid) {
#pragma unroll
    for (int i = 0; i < 4; i++) {
        int lin = tid + i * 128;               // 0..511
        int row = lin >> 2, c8 = (lin & 3) << 3;
        cp16(As + row * ASH + c8,
             A + (size_t)(bm0 + row) * K + (size_t)kt * BKK + c8);
    }
#pragma unroll
    for (int i = 0; i < 4; i++) {
        int lin = tid + i * 128;
        int row = lin >> 2, c8 = (lin & 3) << 3;
        cp16(Bs + row * BSH + c8,
             Bt + (size_t)(bn0 + row) * K + (size_t)kt * BKK + c8);
    }
}

__device__ __forceinline__ void gemm_core(int M, int N, int K,
    const __half* __restrict__ A, const __half* __restrict__ Bt,
    const float* __restrict__ bias, const float* __restrict__ resid,
    void* __restrict__ Cp, int relu, int out_half) {
    extern __shared__ __half smh[];
    const int tid = threadIdx.x;
    const int warp = tid >> 5, lane = tid & 31;
    const int g = lane >> 2, t = lane & 3;
    const int wm0 = (warp & 1) << 6;
    const int wn0 = (warp >> 1) << 6;
    const int bm0 = blockIdx.y * BM, bn0 = blockIdx.x * BN;

    const int sub = lane >> 3, lr = lane & 7;
    const int a_roff = ((sub & 1) << 3) + lr;
    const int a_coff = (sub >> 1) << 3;
    const int b_roff = ((sub >> 1) << 3) + lr;
    const int b_coff = (sub & 1) << 3;

    float acc[4][8][4];
#pragma unroll
    for (int i = 0; i < 4; i++)
#pragma unroll
        for (int j = 0; j < 8; j++)
#pragma unroll
            for (int r = 0; r < 4; r++) acc[i][j][r] = 0.f;

    const int nkt = K / BKK;
    gemm_prefetch(A, Bt, K, bm0, bn0, 0, smh, smh + BM * ASH, tid);
    asm volatile("cp.async.commit_group;");

    int buf = 0;
    for (int kt = 0; kt < nkt; kt++) {
        asm volatile("cp.async.wait_group 0;");
        __syncthreads();
        if (kt + 1 < nkt) {
            __half* As_n = smh + (buf ^ 1) * STAGE_HALVES;
            gemm_prefetch(A, Bt, K, bm0, bn0, kt + 1, As_n,
                          As_n + BM * ASH, tid);
            asm volatile("cp.async.commit_group;");
        }
        const __half* As = smh + buf * STAGE_HALVES;
        const __half* Bs = As + BM * ASH;
        const unsigned a_base = smem_addr(As) +
            ((unsigned)(wm0 + a_roff) * ASH + a_coff) * 2u;
        const unsigned b_base = smem_addr(Bs) +
            ((unsigned)(wn0 + b_roff) * BSH + b_coff) * 2u;
#pragma unroll
        for (int ks = 0; ks < 2; ks++) {
            const unsigned kkb = (unsigned)(ks * 16) * 2u;
            unsigned av[4][4], bv[8][2];
#pragma unroll
            for (int mt = 0; mt < 4; mt++) {
                unsigned addr = a_base + (unsigned)(mt * 16 * ASH) * 2u + kkb;
                LDSM_X4(av[mt][0], av[mt][1], av[mt][2], av[mt][3], addr);
            }
#pragma unroll
            for (int np = 0; np < 4; np++) {
                unsigned addr = b_base + (unsigned)(np * 16 * BSH) * 2u + kkb;
                LDSM_X4(bv[2 * np][0], bv[2 * np][1],
                        bv[2 * np + 1][0], bv[2 * np + 1][1], addr);
            }
#pragma unroll
            for (int mt = 0; mt < 4; mt++)
#pragma unroll
                for (int nt = 0; nt < 8; nt++)
                    MMA_F16(acc[mt][nt], av[mt], bv[nt]);
        }
        buf ^= 1;
    }

#pragma unroll
    for (int mt = 0; mt < 4; mt++) {
#pragma unroll
        for (int nt = 0; nt < 8; nt++) {
            int row = bm0 + wm0 + mt * 16 + g;
            int col = bn0 + wn0 + nt * 8 + t * 2;
            float bb0 = bias[col], bb1 = bias[col + 1];
            float o0 = acc[mt][nt][0] + bb0;
            float o1 = acc[mt][nt][1] + bb1;
            float o2 = acc[mt][nt][2] + bb0;
            float o3 = acc[mt][nt][3] + bb1;
            if (relu) {
                o0 = fmaxf(o0, 0.f); o1 = fmaxf(o1, 0.f);
                o2 = fmaxf(o2, 0.f); o3 = fmaxf(o3, 0.f);
            }
            if (resid) {
                float2 r0 = *reinterpret_cast<const float2*>(
                    resid + (size_t)row * N + col);
                float2 r1 = *reinterpret_cast<const float2*>(
                    resid + (size_t)(row + 8) * N + col);
                o0 += r0.x; o1 += r0.y; o2 += r1.x; o3 += r1.y;
            }
            if (out_half) {
                __half* Ch = (__half*)Cp;
                *reinterpret_cast<__half2*>(Ch + (size_t)row * N + col) =
                    __floats2half2_rn(o0, o1);
                *reinterpret_cast<__half2*>(Ch + (size_t)(row + 8) * N + col) =
                    __floats2half2_rn(o2, o3);
            } else {
                float* Cf = (float*)Cp;
                float2 s0 = {o0, o1}, s1 = {o2, o3};
                *reinterpret_cast<float2*>(Cf + (size_t)row * N + col) = s0;
                *reinterpret_cast<float2*>(Cf + (size_t)(row + 8) * N + col) = s1;
            }
        }
    }
}

__global__ __launch_bounds__(128, 2)
void h_gemm_kernel(int M, int N, int K, const __half* __restrict__ A,
                   const __half* __restrict__ Bt,
                   const float* __restrict__ bias,
                   const float* __restrict__ resid,
                   void* __restrict__ C, int relu, int out_half) {
    gemm_core(M, N, K, A, Bt, bias, resid, C, relu, out_half);
}

struct QkvPtrs {
    const __half* W[3];
    const float* b[3];
    __half* o[3];
};

__global__ __launch_bounds__(128, 2)
void h_gemm_qkv_kernel(const __half* __restrict__ A, QkvPtrs p) {
    int z = blockIdx.z;
    gemm_core(MROWS, DD, DD, A, p.W[z], p.b[z], nullptr, p.o[z], 0, 1);
}

// ---------------------------------------------------------------------------
// Flash attention, fp16 operands, m16n8k16 mma, double-buffered K/V cp.async.
// Softmax exp via ex2.approx.f16x2 (2 exps per MUFU op) — flash is MUFU-bound.
// ---------------------------------------------------------------------------
__device__ __forceinline__ void fl_prefetch_kv(const __half* __restrict__ Kp,
                                               const __half* __restrict__ Vp,
                                               __half* Ks, __half* Vs, int tid) {
#pragma unroll
    for (int i = 0; i < 2; i++) {
        int lin = tid + i * 256;           // 0..511
        int row = lin >> 3, c8 = (lin & 7) << 3;
        cp16(Ks + row * KSH + c8, Kp + (size_t)row * DD + c8);
        cp16(Vs + row * VSH + c8, Vp + (size_t)row * DD + c8);
    }
}

__global__ __launch_bounds__(256, 2)
void flash_tc_kernel(const __half* __restrict__ Q,
                     const __half* __restrict__ Kg,
                     const __half* __restrict__ Vg,
                     const int*   __restrict__ mask,
                     const float* __restrict__ xin,
                     float* __restrict__ out) {
    extern __shared__ char smraw[];
    __half* Qs = (__half*)smraw;                       // [64][QSH]
    __half* Ks = Qs + 64 * QSH;                        // 2x [64][KSH]
    __half* Vs = Ks + 2 * 64 * KSH;                    // 2x [64][VSH]
    float*  Sf = (float*)(Vs + 2 * 64 * VSH);          // [64][SFS]
    __half* Ph = (__half*)(Sf + 64 * SFS);             // [64][PSH]
    float* m_row   = (float*)(Ph + 64 * PSH);
    float* l_row   = m_row + 64;
    float* c_row   = l_row + 64;
    float* any_row = c_row + 64;

    const int tid = threadIdx.x;
    const int warp = tid >> 5, lane = tid & 31;
    const int g = lane >> 2, t = lane & 3;
    const int wm = (warp & 3) << 4;     // 0,16,32,48
    const int wn = (warp >> 2) << 5;    // 0,32
    const int qt = blockIdx.x, h = blockIdx.y, b = blockIdx.z;
    const int q0 = qt * 64;

    const int sub = lane >> 3, lr = lane & 7;
    const int a_roff = ((sub & 1) << 3) + lr;
    const int a_coff = (sub >> 1) << 3;
    const int b_roff = ((sub >> 1) << 3) + lr;
    const int b_coff = (sub & 1) << 3;
    const int vt_roff = ((sub & 1) << 3) + lr;
    const int vt_coff = (sub >> 1) << 3;

    const __half* Qgp = Q + ((size_t)(b * TT + q0) * DD + h * DH);
    const int sr = tid >> 2, spart = tid & 3;
    const int sks0 = spart * 16;
    const int* maskrow = mask + (size_t)b * TT * TT + (size_t)(q0 + sr) * TT + sks0;

    // prologue: prefetch Q + K/V tile 0
#pragma unroll
    for (int i = 0; i < 2; i++) {
        int lin = tid + i * 256;
        int row = lin >> 3, c8 = (lin & 7) << 3;
        cp16(Qs + row * QSH + c8, Qgp + (size_t)row * DD + c8);
    }
    fl_prefetch_kv(Kg + ((size_t)(b * TT) * DD + h * DH),
                   Vg + ((size_t)(b * TT) * DD + h * DH), Ks, Vs, tid);
    asm volatile("cp.async.commit_group;");

    if (tid < 64) {
        m_row[tid] = -INFINITY;
        l_row[tid] = 0.f;
        any_row[tid] = 0.f;
    }
    float oacc[4][4];
#pragma unroll
    for (int nt = 0; nt < 4; nt++)
#pragma unroll
        for (int r = 0; r < 4; r++) oacc[nt][r] = 0.f;

    const unsigned q_base = smem_addr(Qs) +
        ((unsigned)(wm + a_roff) * QSH + a_coff) * 2u;
    const unsigned p_base = smem_addr(Ph) +
        ((unsigned)(wm + a_roff) * PSH + a_coff) * 2u;
    const float LOG2E = 1.4426950408889634f;

    for (int kt = 0; kt < TT / 64; kt++) {
        const int bufi = kt & 1;
        const __half* Kb = Ks + bufi * 64 * KSH;
        const __half* Vb = Vs + bufi * 64 * VSH;

        asm volatile("cp.async.wait_group 0;");
        __syncthreads();
        if (kt + 1 < TT / 64) {
            const int k1 = (kt + 1) * 64;
            fl_prefetch_kv(Kg + ((size_t)(b * TT + k1) * DD + h * DH),
                           Vg + ((size_t)(b * TT + k1) * DD + h * DH),
                           Ks + (bufi ^ 1) * 64 * KSH,
                           Vs + (bufi ^ 1) * 64 * VSH, tid);
            asm volatile("cp.async.commit_group;");
        }

        // early mask loads (hidden by S-mma)
        const int4* mp = reinterpret_cast<const int4*>(maskrow + kt * 64);
        int4 m0 = mp[0], m1 = mp[1], m2 = mp[2], m3 = mp[3];

        // ---- S = Q K^T ----
        float sacc[4][4];
#pragma unroll
        for (int nt = 0; nt < 4; nt++)
#pragma unroll
            for (int r = 0; r < 4; r++) sacc[nt][r] = 0.f;
        const unsigned kb_base = smem_addr(Kb) +
            ((unsigned)(wn + b_roff) * KSH + b_coff) * 2u;
#pragma unroll
        for (int ks = 0; ks < 4; ks++) {
            const unsigned kkb = (unsigned)(ks * 16) * 2u;
            unsigned a[4], bv[4][2];
            LDSM_X4(a[0], a[1], a[2], a[3], q_base + kkb);
#pragma unroll
            for (int np = 0; np < 2; np++) {
                unsigned addr = kb_base + (unsigned)(np * 16 * KSH) * 2u + kkb;
                LDSM_X4(bv[2 * np][0], bv[2 * np][1],
                        bv[2 * np + 1][0], bv[2 * np + 1][1], addr);
            }
#pragma unroll
            for (int nt = 0; nt < 4; nt++)
                MMA_F16(sacc[nt], a, bv[nt]);
        }
#pragma unroll
        for (int nt = 0; nt < 4; nt++) {
            int col = wn + nt * 8 + 2 * t;
            float2 s0 = {sacc[nt][0] * 0.125f, sacc[nt][1] * 0.125f};
            float2 s1 = {sacc[nt][2] * 0.125f, sacc[nt][3] * 0.125f};
            *reinterpret_cast<float2*>(Sf + (wm + g) * SFS + col) = s0;
            *reinterpret_cast<float2*>(Sf + (wm + g + 8) * SFS + col) = s1;
        }
        __syncthreads();

        // ---- online softmax (4 threads per row), exp via ex2.f16x2 ----
        {
            int mm[16] = {m0.x, m0.y, m0.z, m0.w, m1.x, m1.y, m1.z, m1.w,
                          m2.x, m2.y, m2.z, m2.w, m3.x, m3.y, m3.z, m3.w};
            float sv[16];
            float mx = -INFINITY;
            int anyl = 0;
#pragma unroll
            for (int k = 0; k < 16; k++) {
                float s = Sf[sr * SFS + sks0 + k] + (mm[k] ? 0.f : -1e9f);
                sv[k] = s;
                mx = fmaxf(mx, s);
                anyl |= mm[k];
            }
            mx = fmaxf(mx, __shfl_xor_sync(0xffffffffu, mx, 1));
            mx = fmaxf(mx, __shfl_xor_sync(0xffffffffu, mx, 2));
            float mold = m_row[sr];
            float mnew = fmaxf(mold, mx);
            float psum = 0.f;
#pragma unroll
            for (int k = 0; k < 16; k += 2) {
                float y0 = (sv[k] - mnew) * LOG2E;
                float y1 = (sv[k + 1] - mnew) * LOG2E;
                __half2 yh = __floats2half2_rn(y0, y1);
                unsigned e2 = ex2_f16x2(*reinterpret_cast<unsigned*>(&yh));
                *reinterpret_cast<unsigned*>(Ph + sr * PSH + sks0 + k) = e2;
                float2 ef = __half22float2(*reinterpret_cast<__half2*>(&e2));
                psum += ef.x + ef.y;
            }
            psum += __shfl_xor_sync(0xffffffffu, psum, 1);
            psum += __shfl_xor_sync(0xffffffffu, psum, 2);
            if (anyl) any_row[sr] = 1.f;
            if (spart == 0) {
                float c = __expf(mold - mnew);
                c_row[sr] = c;
                l_row[sr] = l_row[sr] * c + psum;
                m_row[sr] = mnew;
            }
        }
        __syncthreads();

        // ---- O = O*c + P @ V ----
        {
            float c0 = c_row[wm + g];
            float c1 = c_row[wm + g + 8];
#pragma unroll
            for (int nt = 0; nt < 4; nt++) {
                oacc[nt][0] *= c0; oacc[nt][1] *= c0;
                oacc[nt][2] *= c1; oacc[nt][3] *= c1;
            }
            const unsigned v_base = smem_addr(Vb) +
                ((unsigned)vt_roff * VSH + wn + vt_coff) * 2u;
#pragma unroll
            for (int ks = 0; ks < 4; ks++) {
                const unsigned kkb = (unsigned)(ks * 16) * 2u;
                unsigned a[4], bv[4][2];
                LDSM_X4(a[0], a[1], a[2], a[3], p_base + kkb);
#pragma unroll
                for (int np = 0; np < 2; np++) {
                    unsigned addr = v_base + (unsigned)(ks * 16 * VSH) * 2u +
                                    (unsigned)(np * 16) * 2u;
                    LDSM_X4_T(bv[2 * np][0], bv[2 * np][1],
                              bv[2 * np + 1][0], bv[2 * np + 1][1], addr);
                }
#pragma unroll
                for (int nt = 0; nt < 4; nt++)
                    MMA_F16(oacc[nt], a, bv[nt]);
            }
        }
        __syncthreads();
    }

    // ---- epilogue: normalize, zero fully-masked rows, add residual x ----
    {
        int r0 = wm + g, r1 = wm + g + 8;
        float inv0 = (any_row[r0] != 0.f) ? (1.f / l_row[r0]) : 0.f;
        float inv1 = (any_row[r1] != 0.f) ? (1.f / l_row[r1]) : 0.f;
#pragma unroll
        for (int nt = 0; nt < 4; nt++) {
            int col = h * DH + wn + nt * 8 + 2 * t;
            size_t base0 = (size_t)(b * TT + q0 + r0) * DD + col;
            size_t base1 = (size_t)(b * TT + q0 + r1) * DD + col;
            float2 x0 = *reinterpret_cast<const float2*>(xin + base0);
            float2 x1 = *reinterpret_cast<const float2*>(xin + base1);
            float2 o0 = {oacc[nt][0] * inv0 + x0.x, oacc[nt][1] * inv0 + x0.y};
            float2 o1 = {oacc[nt][2] * inv1 + x1.x, oacc[nt][3] * inv1 + x1.y};
            *reinterpret_cast<float2*>(out + base0) = o0;
            *reinterpret_cast<float2*>(out + base1) = o1;
        }
    }
}

// ---------------------------------------------------------------------------
// Launch
// ---------------------------------------------------------------------------
extern "C" void kernel_launch(void* const* d_in, const int* in_sizes, int n_in,
                              void* d_out, int out_size) {
    const float* x     = (const float*)d_in[0];
    const int*   mask  = (const int*)  d_in[1];
    const float* Wq    = (const float*)d_in[2];
    const float* bq    = (const float*)d_in[3];
    const float* Wk    = (const float*)d_in[4];
    const float* bk    = (const float*)d_in[5];
    const float* Wv    = (const float*)d_in[6];
    const float* bv    = (const float*)d_in[7];
    const float* g_in  = (const float*)d_in[8];
    const float* b_in  = (const float*)d_in[9];
    const float* g1    = (const float*)d_in[10];
    const float* b1    = (const float*)d_in[11];
    const float* W_ff1 = (const float*)d_in[12];
    const float* b_ff1 = (const float*)d_in[13];
    const float* W_ff2 = (const float*)d_in[14];
    const float* b_ff2 = (const float*)d_in[15];
    const float* g2    = (const float*)d_in[16];
    const float* b2    = (const float*)d_in[17];
    float* out = (float*)d_out;

    __half *xn_h, *q_h, *k_h, *v_h, *h1n_h, *ff_h;
    __half *wq_h, *wk_h, *wv_h, *w1_h, *w2_h;
    float *res1, *res2;
    cudaGetSymbolAddress((void**)&xn_h,  g_xn_h);
    cudaGetSymbolAddress((void**)&q_h,   g_q_h);
    cudaGetSymbolAddress((void**)&k_h,   g_k_h);
    cudaGetSymbolAddress((void**)&v_h,   g_v_h);
    cudaGetSymbolAddress((void**)&h1n_h, g_h1n_h);
    cudaGetSymbolAddress((void**)&ff_h,  g_ff_h);
    cudaGetSymbolAddress((void**)&res1,  g_res1);
    cudaGetSymbolAddress((void**)&res2,  g_res2);
    cudaGetSymbolAddress((void**)&wq_h,  g_wq_h);
    cudaGetSymbolAddress((void**)&wk_h,  g_wk_h);
    cudaGetSymbolAddress((void**)&wv_h,  g_wv_h);
    cudaGetSymbolAddress((void**)&w1_h,  g_w1_h);
    cudaGetSymbolAddress((void**)&w2_h,  g_w2_h);

    cudaFuncSetAttribute(flash_tc_kernel,
                         cudaFuncAttributeMaxDynamicSharedMemorySize, FL_SMEM_BYTES);
    cudaFuncSetAttribute(h_gemm_kernel,
                         cudaFuncAttributeMaxDynamicSharedMemorySize, GEMM_SMEM);
    cudaFuncSetAttribute(h_gemm_qkv_kernel,
                         cudaFuncAttributeMaxDynamicSharedMemorySize, GEMM_SMEM);

    // 0. weight -> fp16 transposed copies w[n][k]
    {
        CvtTJobs jq;
        jq.in[0] = Wq; jq.in[1] = Wk; jq.in[2] = Wv;
        jq.out[0] = wq_h; jq.out[1] = wk_h; jq.out[2] = wv_h;
        cvt_half_T_kernel<<<dim3(DD / 32, DD / 32, 3), dim3(32, 8)>>>(jq, DD, DD);
        CvtTJobs j1;
        j1.in[0] = W_ff1; j1.in[1] = nullptr; j1.in[2] = nullptr;
        j1.out[0] = w1_h;
        cvt_half_T_kernel<<<dim3(FFN / 32, DD / 32, 1), dim3(32, 8)>>>(j1, DD, FFN);
        CvtTJobs j2;
        j2.in[0] = W_ff2; j2.in[1] = nullptr; j2.in[2] = nullptr;
        j2.out[0] = w2_h;
        cvt_half_T_kernel<<<dim3(DD / 32, FFN / 32, 1), dim3(32, 8)>>>(j2, FFN, DD);
    }

    // 1. pre-LN -> fp16
    ln1024_kernel<<<MROWS, 256>>>(x, g_in, b_in, nullptr, xn_h);

    // 2. QKV projections (fused grid.z; fp16 outputs)
    {
        QkvPtrs p;
        p.W[0] = wq_h; p.W[1] = wk_h; p.W[2] = wv_h;
        p.b[0] = bq;   p.b[1] = bk;   p.b[2] = bv;
        p.o[0] = q_h;  p.o[1] = k_h;  p.o[2] = v_h;
        h_gemm_qkv_kernel<<<dim3(DD / BN, MROWS / BM, 3), 128, GEMM_SMEM>>>(xn_h, p);
    }

    // 3. attention + residual(x) -> res1 (fp32)
    flash_tc_kernel<<<dim3(TT / 64, HH, BB), 256, FL_SMEM_BYTES>>>(
        q_h, k_h, v_h, mask, x, res1);

    // 4. LN -> fp16
    ln1024_kernel<<<MROWS, 256>>>(res1, g1, b1, nullptr, h1n_h);

    // 5. FF1 + relu -> fp16
    h_gemm_kernel<<<dim3(FFN / BN, MROWS / BM), 128, GEMM_SMEM>>>(
        MROWS, FFN, DD, h1n_h, w1_h, b_ff1, nullptr, ff_h, 1, 1);

    // 6. FF2 + bias + residual(res1) -> fp32
    h_gemm_kernel<<<dim3(DD / BN, MROWS / BM), 128, GEMM_SMEM>>>(
        MROWS, DD, FFN, ff_h, w2_h, b_ff2, res1, res2, 0, 0);

    // 7. final LN -> out (fp32)
    ln1024_kernel<<<MROWS, 256>>>(res2, g2, b2, out, nullptr);
}

// round 14
// speedup vs baseline: 1.1862x; 1.1862x over previous
#include <cuda_runtime.h>
#include <cuda_fp16.h>
#include <math.h>
#include <stdint.h>

// Problem constants
#define BB 2
#define TT 2048
#define DD 1024
#define HH 16
#define DH 64
#define FFN 4096
#define MROWS (BB*TT)          // 4096
#define LN_EPS 1e-3f

// FP16 GEMM tiling: 128x128x32 block, 128 threads (4 warps), warp tile 64x64
#define BM 128
#define BN 128
#define BKK 32                  // k-halves per stage
#define ASH 40                  // A smem row stride (halves)
#define BSH 40
#define STAGE_HALVES (BM*ASH + BN*BSH)      // 10240
#define GEMM_SMEM (2*STAGE_HALVES*2)        // 40960 bytes

// Flash tiling (fp16, FA2-style register pipeline)
// CTA: 128 q-rows, k-tiles of 64. 8 warps, warp = 16 q-rows x full 64 k-cols.
#define QSH 72                  // [q][d] halves
#define KSH 72                  // [t][d] halves
#define VSH 72                  // [t][d] halves
#define FL_SMEM_BYTES ((128*QSH + 2*64*KSH + 2*64*VSH)*2)   // 55296

// ---------------------------------------------------------------------------
// Scratch (device globals; no allocation allowed)
// ---------------------------------------------------------------------------
__device__ __half g_xn_h [MROWS*DD];
__device__ __half g_q_h  [MROWS*DD];
__device__ __half g_k_h  [MROWS*DD];
__device__ __half g_v_h  [MROWS*DD];
__device__ __half g_h1n_h[MROWS*DD];
__device__ __half g_ff_h [MROWS*FFN];
__device__ float  g_res1 [MROWS*DD];
__device__ float  g_res2 [MROWS*DD];
// fp16 TRANSPOSED weight copies w[n][k]
__device__ __half g_wq_h[DD*DD];
__device__ __half g_wk_h[DD*DD];
__device__ __half g_wv_h[DD*DD];
__device__ __half g_w1_h[FFN*DD];
__device__ __half g_w2_h[DD*FFN];

// ---------------------------------------------------------------------------
// Helpers
// ---------------------------------------------------------------------------
__device__ __forceinline__ void cp16(void* dst, const void* src) {
    unsigned s = (unsigned)__cvta_generic_to_shared(dst);
    asm volatile("cp.async.cg.shared.global [%0], [%1], 16;" :: "r"(s), "l"(src));
}

__device__ __forceinline__ unsigned smem_addr(const void* p) {
    return (unsigned)__cvta_generic_to_shared(p);
}

#define MMA_F16(c, a, b) \
    asm volatile("mma.sync.aligned.m16n8k16.row.col.f32.f16.f16.f32 " \
        "{%0,%1,%2,%3}, {%4,%5,%6,%7}, {%8,%9}, {%0,%1,%2,%3};" \
        : "+f"((c)[0]), "+f"((c)[1]), "+f"((c)[2]), "+f"((c)[3]) \
        : "r"((a)[0]), "r"((a)[1]), "r"((a)[2]), "r"((a)[3]), \
          "r"((b)[0]), "r"((b)[1]))

#define LDSM_X4(r0, r1, r2, r3, addr) \
    asm volatile("ldmatrix.sync.aligned.m8n8.x4.shared.b16 {%0,%1,%2,%3}, [%4];" \
        : "=r"(r0), "=r"(r1), "=r"(r2), "=r"(r3) : "r"(addr))

#define LDSM_X4_T(r0, r1, r2, r3, addr) \
    asm volatile("ldmatrix.sync.aligned.m8n8.x4.trans.shared.b16 {%0,%1,%2,%3}, [%4];" \
        : "=r"(r0), "=r"(r1), "=r"(r2), "=r"(r3) : "r"(addr))

// two fp16 exponentials (base-2) in ONE MUFU op
__device__ __forceinline__ unsigned ex2_f16x2(unsigned y) {
    unsigned r;
    asm("ex2.approx.f16x2 %0, %1;" : "=r"(r) : "r"(y));
    return r;
}

// ---------------------------------------------------------------------------
// Weight -> fp16 (rn) + transpose: in[K][N] fp32 -> out[N][K] half
// ---------------------------------------------------------------------------
struct CvtTJobs {
    const float* in[3];
    __half* out[3];
};

__global__ void cvt_half_T_kernel(CvtTJobs j, int K, int N) {
    __shared__ float tile[32][33];
    int z = blockIdx.z;
    if (!j.in[z]) return;
    const float* in = j.in[z];
    __half* outp = j.out[z];
    int n0 = blockIdx.x * 32, k0 = blockIdx.y * 32;
    int tx = threadIdx.x, ty = threadIdx.y;   // 32 x 8
#pragma unroll
    for (int i = 0; i < 4; i++)
        tile[ty + 8 * i][tx] = in[(size_t)(k0 + ty + 8 * i) * N + n0 + tx];
    __syncthreads();
#pragma unroll
    for (int i = 0; i < 4; i++)
        outp[(size_t)(n0 + ty + 8 * i) * K + k0 + tx] =
            __float2half_rn(tile[tx][ty + 8 * i]);
}

// ---------------------------------------------------------------------------
// LayerNorm over last dim (D=1024); writes fp32 OR fp16 output
// ---------------------------------------------------------------------------
__device__ __forceinline__ float block_reduce_sum_256(float v, float* red) {
    __syncthreads();
#pragma unroll
    for (int o = 16; o > 0; o >>= 1) v += __shfl_xor_sync(0xffffffffu, v, o);
    int lane = threadIdx.x & 31, wid = threadIdx.x >> 5;
    if (lane == 0) red[wid] = v;
    __syncthreads();
    if (wid == 0) {
        v = (lane < 8) ? red[lane] : 0.f;
#pragma unroll
        for (int o = 4; o > 0; o >>= 1) v += __shfl_xor_sync(0xffffffffu, v, o);
        if (lane == 0) red[0] = v;
    }
    __syncthreads();
    return red[0];
}

__global__ void ln1024_kernel(const float* __restrict__ x,
                              const float* __restrict__ gamma,
                              const float* __restrict__ beta,
                              float* __restrict__ outf,
                              __half* __restrict__ outh) {
    __shared__ float red[8];
    int row = blockIdx.x;
    int t = threadIdx.x;
    const float4 v = reinterpret_cast<const float4*>(x + (size_t)row * DD)[t];

    float s = v.x + v.y + v.z + v.w;
    float mu = block_reduce_sum_256(s, red) * (1.0f / DD);

    float dx = v.x - mu, dy = v.y - mu, dz = v.z - mu, dw = v.w - mu;
    float q = dx*dx + dy*dy + dz*dz + dw*dw;
    float var = block_reduce_sum_256(q, red) * (1.0f / DD);
    float r = rsqrtf(var + LN_EPS);

    const float4 gg = reinterpret_cast<const float4*>(gamma)[t];
    const float4 bb = reinterpret_cast<const float4*>(beta)[t];
    float o0 = dx * r * gg.x + bb.x;
    float o1 = dy * r * gg.y + bb.y;
    float o2 = dz * r * gg.z + bb.z;
    float o3 = dw * r * gg.w + bb.w;
    if (outh) {
        __half2 h0 = __floats2half2_rn(o0, o1);
        __half2 h1 = __floats2half2_rn(o2, o3);
        reinterpret_cast<__half2*>(outh + (size_t)row * DD)[2 * t] = h0;
        reinterpret_cast<__half2*>(outh + (size_t)row * DD)[2 * t + 1] = h1;
    } else {
        float4 o = {o0, o1, o2, o3};
        reinterpret_cast<float4*>(outf + (size_t)row * DD)[t] = o;
    }
}

// ---------------------------------------------------------------------------
// FP16 tensor-core GEMM (unchanged)
// ---------------------------------------------------------------------------
__device__ __forceinline__ void gemm_prefetch(const __half* __restrict__ A,
                                              const __half* __restrict__ Bt,
                                              int K, int bm0, int bn0,
                                              int kt, __half* As, __half* Bs,
                                              int tid) {
#pragma unroll
    for (int i = 0; i < 4; i++) {
        int lin = tid + i * 128;               // 0..511
        int row = lin >> 2, c8 = (lin & 3) << 3;
        cp16(As + row * ASH + c8,
             A + (size_t)(bm0 + row) * K + (size_t)kt * BKK + c8);
    }
#pragma unroll
    for (int i = 0; i < 4; i++) {
        int lin = tid + i * 128;
        int row = lin >> 2, c8 = (lin & 3) << 3;
        cp16(Bs + row * BSH + c8,
             Bt + (size_t)(bn0 + row) * K + (size_t)kt * BKK + c8);
    }
}

__device__ __forceinline__ void gemm_core(int M, int N, int K,
    const __half* __restrict__ A, const __half* __restrict__ Bt,
    const float* __restrict__ bias, const float* __restrict__ resid,
    void* __restrict__ Cp, int relu, int out_half) {
    extern __shared__ __half smh[];
    const int tid = threadIdx.x;
    const int warp = tid >> 5, lane = tid & 31;
    const int g = lane >> 2, t = lane & 3;
    const int wm0 = (warp & 1) << 6;
    const int wn0 = (warp >> 1) << 6;
    const int bm0 = blockIdx.y * BM, bn0 = blockIdx.x * BN;

    const int sub = lane >> 3, lr = lane & 7;
    const int a_roff = ((sub & 1) << 3) + lr;
    const int a_coff = (sub >> 1) << 3;
    const int b_roff = ((sub >> 1) << 3) + lr;
    const int b_coff = (sub & 1) << 3;

    float acc[4][8][4];
#pragma unroll
    for (int i = 0; i < 4; i++)
#pragma unroll
        for (int j = 0; j < 8; j++)
#pragma unroll
            for (int r = 0; r < 4; r++) acc[i][j][r] = 0.f;

    const int nkt = K / BKK;
    gemm_prefetch(A, Bt, K, bm0, bn0, 0, smh, smh + BM * ASH, tid);
    asm volatile("cp.async.commit_group;");

    int buf = 0;
    for (int kt = 0; kt < nkt; kt++) {
        asm volatile("cp.async.wait_group 0;");
        __syncthreads();
        if (kt + 1 < nkt) {
            __half* As_n = smh + (buf ^ 1) * STAGE_HALVES;
            gemm_prefetch(A, Bt, K, bm0, bn0, kt + 1, As_n,
                          As_n + BM * ASH, tid);
            asm volatile("cp.async.commit_group;");
        }
        const __half* As = smh + buf * STAGE_HALVES;
        const __half* Bs = As + BM * ASH;
        const unsigned a_base = smem_addr(As) +
            ((unsigned)(wm0 + a_roff) * ASH + a_coff) * 2u;
        const unsigned b_base = smem_addr(Bs) +
            ((unsigned)(wn0 + b_roff) * BSH + b_coff) * 2u;
#pragma unroll
        for (int ks = 0; ks < 2; ks++) {
            const unsigned kkb = (unsigned)(ks * 16) * 2u;
            unsigned av[4][4], bv[8][2];
#pragma unroll
            for (int mt = 0; mt < 4; mt++) {
                unsigned addr = a_base + (unsigned)(mt * 16 * ASH) * 2u + kkb;
                LDSM_X4(av[mt][0], av[mt][1], av[mt][2], av[mt][3], addr);
            }
#pragma unroll
            for (int np = 0; np < 4; np++) {
                unsigned addr = b_base + (unsigned)(np * 16 * BSH) * 2u + kkb;
                LDSM_X4(bv[2 * np][0], bv[2 * np][1],
                        bv[2 * np + 1][0], bv[2 * np + 1][1], addr);
            }
#pragma unroll
            for (int mt = 0; mt < 4; mt++)
#pragma unroll
                for (int nt = 0; nt < 8; nt++)
                    MMA_F16(acc[mt][nt], av[mt], bv[nt]);
        }
        buf ^= 1;
    }

#pragma unroll
    for (int mt = 0; mt < 4; mt++) {
#pragma unroll
        for (int nt = 0; nt < 8; nt++) {
            int row = bm0 + wm0 + mt * 16 + g;
            int col = bn0 + wn0 + nt * 8 + t * 2;
            float bb0 = bias[col], bb1 = bias[col + 1];
            float o0 = acc[mt][nt][0] + bb0;
            float o1 = acc[mt][nt][1] + bb1;
            float o2 = acc[mt][nt][2] + bb0;
            float o3 = acc[mt][nt][3] + bb1;
            if (relu) {
                o0 = fmaxf(o0, 0.f); o1 = fmaxf(o1, 0.f);
                o2 = fmaxf(o2, 0.f); o3 = fmaxf(o3, 0.f);
            }
            if (resid) {
                float2 r0 = *reinterpret_cast<const float2*>(
                    resid + (size_t)row * N + col);
                float2 r1 = *reinterpret_cast<const float2*>(
                    resid + (size_t)(row + 8) * N + col);
                o0 += r0.x; o1 += r0.y; o2 += r1.x; o3 += r1.y;
            }
            if (out_half) {
                __half* Ch = (__half*)Cp;
                *reinterpret_cast<__half2*>(Ch + (size_t)row * N + col) =
                    __floats2half2_rn(o0, o1);
                *reinterpret_cast<__half2*>(Ch + (size_t)(row + 8) * N + col) =
                    __floats2half2_rn(o2, o3);
            } else {
                float* Cf = (float*)Cp;
                float2 s0 = {o0, o1}, s1 = {o2, o3};
                *reinterpret_cast<float2*>(Cf + (size_t)row * N + col) = s0;
                *reinterpret_cast<float2*>(Cf + (size_t)(row + 8) * N + col) = s1;
            }
        }
    }
}

__global__ __launch_bounds__(128, 2)
void h_gemm_kernel(int M, int N, int K, const __half* __restrict__ A,
                   const __half* __restrict__ Bt,
                   const float* __restrict__ bias,
                   const float* __restrict__ resid,
                   void* __restrict__ C, int relu, int out_half) {
    gemm_core(M, N, K, A, Bt, bias, resid, C, relu, out_half);
}

struct QkvPtrs {
    const __half* W[3];
    const float* b[3];
    __half* o[3];
};

__global__ __launch_bounds__(128, 2)
void h_gemm_qkv_kernel(const __half* __restrict__ A, QkvPtrs p) {
    int z = blockIdx.z;
    gemm_core(MROWS, DD, DD, A, p.W[z], p.b[z], nullptr, p.o[z], 0, 1);
}

// ---------------------------------------------------------------------------
// Flash attention, FA2-style: register-resident S->P pipeline.
// CTA = (b, h, 128 q-rows). 8 warps; warp = 16 q-rows x full 64 k-cols.
// S C-fragments become PV A-fragments directly (half2 pack after exp).
// Row softmax stats in registers (quad shfl). ONE barrier per k-tile.
// ---------------------------------------------------------------------------
__device__ __forceinline__ void fl_prefetch_kv(const __half* __restrict__ Kp,
                                               const __half* __restrict__ Vp,
                                               __half* Ks, __half* Vs, int tid) {
#pragma unroll
    for (int i = 0; i < 2; i++) {
        int lin = tid + i * 256;           // 0..511
        int row = lin >> 3, c8 = (lin & 7) << 3;
        cp16(Ks + row * KSH + c8, Kp + (size_t)row * DD + c8);
        cp16(Vs + row * VSH + c8, Vp + (size_t)row * DD + c8);
    }
}

__global__ __launch_bounds__(256, 2)
void flash_tc_kernel(const __half* __restrict__ Q,
                     const __half* __restrict__ Kg,
                     const __half* __restrict__ Vg,
                     const int*   __restrict__ mask,
                     const float* __restrict__ xin,
                     float* __restrict__ out) {
    extern __shared__ char smraw[];
    __half* Qs = (__half*)smraw;                       // [128][QSH]
    __half* Ks = Qs + 128 * QSH;                       // 2x [64][KSH]
    __half* Vs = Ks + 2 * 64 * KSH;                    // 2x [64][VSH]

    const int tid = threadIdx.x;
    const int warp = tid >> 5, lane = tid & 31;
    const int g = lane >> 2, t = lane & 3;
    const int wm = warp << 4;           // warp q-row base: 0..112
    const int qt = blockIdx.x, h = blockIdx.y, b = blockIdx.z;
    const int q0 = qt * 128;

    const int sub = lane >> 3, lr = lane & 7;
    const int a_roff = ((sub & 1) << 3) + lr;
    const int a_coff = (sub >> 1) << 3;
    const int b_roff = ((sub >> 1) << 3) + lr;
    const int b_coff = (sub & 1) << 3;
    const int vt_roff = ((sub & 1) << 3) + lr;
    const int vt_coff = (sub >> 1) << 3;

    const __half* Qgp = Q + ((size_t)(b * TT + q0) * DD + h * DH);
    // per-thread mask row bases (rows wm+g and wm+g+8)
    const int* mb0 = mask + (size_t)b * TT * TT + (size_t)(q0 + wm + g) * TT + 2 * t;
    const int* mb1 = mb0 + 8 * TT;

    // prologue: prefetch Q (128 rows) + K/V tile 0
#pragma unroll
    for (int i = 0; i < 4; i++) {
        int lin = tid + i * 256;           // 0..1023
        int row = lin >> 3, c8 = (lin & 7) << 3;
        cp16(Qs + row * QSH + c8, Qgp + (size_t)row * DD + c8);
    }
    fl_prefetch_kv(Kg + ((size_t)(b * TT) * DD + h * DH),
                   Vg + ((size_t)(b * TT) * DD + h * DH), Ks, Vs, tid);
    asm volatile("cp.async.commit_group;");

    // register state
    float m0 = -INFINITY, m1 = -INFINITY, l0 = 0.f, l1 = 0.f;
    int any0 = 0, any1 = 0;
    float oacc[8][4];
#pragma unroll
    for (int nt = 0; nt < 8; nt++)
#pragma unroll
        for (int r = 0; r < 4; r++) oacc[nt][r] = 0.f;

    const unsigned q_base = smem_addr(Qs) +
        ((unsigned)(wm + a_roff) * QSH + a_coff) * 2u;
    const float LOG2E = 1.4426950408889634f;

    for (int kt = 0; kt < TT / 64; kt++) {
        const int bufi = kt & 1;
        const __half* Kb = Ks + bufi * 64 * KSH;
        const __half* Vb = Vs + bufi * 64 * VSH;

        asm volatile("cp.async.wait_group 0;");
        __syncthreads();
        if (kt + 1 < TT / 64) {
            const int k1 = (kt + 1) * 64;
            fl_prefetch_kv(Kg + ((size_t)(b * TT + k1) * DD + h * DH),
                           Vg + ((size_t)(b * TT + k1) * DD + h * DH),
                           Ks + (bufi ^ 1) * 64 * KSH,
                           Vs + (bufi ^ 1) * 64 * VSH, tid);
            asm volatile("cp.async.commit_group;");
        }

        // mask bits for this tile: rows wm+g / wm+g+8, cols 8nt+2t,+1
        unsigned mbits0 = 0, mbits1 = 0;
#pragma unroll
        for (int nt = 0; nt < 8; nt++) {
            int2 ma = *reinterpret_cast<const int2*>(mb0 + kt * 64 + nt * 8);
            int2 mbv = *reinterpret_cast<const int2*>(mb1 + kt * 64 + nt * 8);
            mbits0 |= (ma.x ? 1u : 0u) << (2 * nt);
            mbits0 |= (ma.y ? 1u : 0u) << (2 * nt + 1);
            mbits1 |= (mbv.x ? 1u : 0u) << (2 * nt);
            mbits1 |= (mbv.y ? 1u : 0u) << (2 * nt + 1);
        }
        any0 |= (mbits0 != 0);
        any1 |= (mbits1 != 0);

        // ---- S = Q K^T: warp computes 16q x 64k ----
        float sacc[8][4];
#pragma unroll
        for (int nt = 0; nt < 8; nt++)
#pragma unroll
            for (int r = 0; r < 4; r++) sacc[nt][r] = 0.f;
        const unsigned kb_base = smem_addr(Kb) +
            ((unsigned)b_roff * KSH + b_coff) * 2u;
#pragma unroll
        for (int ks = 0; ks < 4; ks++) {
            const unsigned kkb = (unsigned)(ks * 16) * 2u;
            unsigned a[4], bv[8][2];
            LDSM_X4(a[0], a[1], a[2], a[3], q_base + kkb);
#pragma unroll
            for (int np = 0; np < 4; np++) {
                unsigned addr = kb_base + (unsigned)(np * 16 * KSH) * 2u + kkb;
                LDSM_X4(bv[2 * np][0], bv[2 * np][1],
                        bv[2 * np + 1][0], bv[2 * np + 1][1], addr);
            }
#pragma unroll
            for (int nt = 0; nt < 8; nt++)
                MMA_F16(sacc[nt], a, bv[nt]);
        }

        // ---- scale + mask + row max (registers + quad shfl) ----
        float mx0 = -INFINITY, mx1 = -INFINITY;
#pragma unroll
        for (int nt = 0; nt < 8; nt++) {
            float b0 = ((mbits0 >> (2 * nt)) & 1) ? 0.f : -1e9f;
            float b1 = ((mbits0 >> (2 * nt + 1)) & 1) ? 0.f : -1e9f;
            float b2 = ((mbits1 >> (2 * nt)) & 1) ? 0.f : -1e9f;
            float b3 = ((mbits1 >> (2 * nt + 1)) & 1) ? 0.f : -1e9f;
            sacc[nt][0] = sacc[nt][0] * 0.125f + b0;
            sacc[nt][1] = sacc[nt][1] * 0.125f + b1;
            sacc[nt][2] = sacc[nt][2] * 0.125f + b2;
            sacc[nt][3] = sacc[nt][3] * 0.125f + b3;
            mx0 = fmaxf(mx0, fmaxf(sacc[nt][0], sacc[nt][1]));
            mx1 = fmaxf(mx1, fmaxf(sacc[nt][2], sacc[nt][3]));
        }
        mx0 = fmaxf(mx0, __shfl_xor_sync(0xffffffffu, mx0, 1));
        mx0 = fmaxf(mx0, __shfl_xor_sync(0xffffffffu, mx0, 2));
        mx1 = fmaxf(mx1, __shfl_xor_sync(0xffffffffu, mx1, 1));
        mx1 = fmaxf(mx1, __shfl_xor_sync(0xffffffffu, mx1, 2));
        float mnew0 = fmaxf(m0, mx0);
        float mnew1 = fmaxf(m1, mx1);
        float c0 = __expf(m0 - mnew0);   // 0 on first tile
        float c1 = __expf(m1 - mnew1);
        m0 = mnew0; m1 = mnew1;

        // rescale O before accumulating this tile
#pragma unroll
        for (int nt = 0; nt < 8; nt++) {
            oacc[nt][0] *= c0; oacc[nt][1] *= c0;
            oacc[nt][2] *= c1; oacc[nt][3] *= c1;
        }

        // ---- exp (f16x2) fused with PV mma; P frags straight from sacc ----
        float psum0 = 0.f, psum1 = 0.f;
        const unsigned v_base = smem_addr(Vb) +
            ((unsigned)vt_roff * VSH + vt_coff) * 2u;
#pragma unroll
        for (int ks = 0; ks < 4; ks++) {
            // P A-fragment for this k16 step from sacc[2ks], sacc[2ks+1]
            unsigned pa[4];
            {
                float* s0 = sacc[2 * ks];
                float* s1 = sacc[2 * ks + 1];
                __half2 y0 = __floats2half2_rn((s0[0] - mnew0) * LOG2E,
                                               (s0[1] - mnew0) * LOG2E);
                __half2 y1 = __floats2half2_rn((s0[2] - mnew1) * LOG2E,
                                               (s0[3] - mnew1) * LOG2E);
                __half2 y2 = __floats2half2_rn((s1[0] - mnew0) * LOG2E,
                                               (s1[1] - mnew0) * LOG2E);
                __half2 y3 = __floats2half2_rn((s1[2] - mnew1) * LOG2E,
                                               (s1[3] - mnew1) * LOG2E);
                pa[0] = ex2_f16x2(*reinterpret_cast<unsigned*>(&y0));
                pa[1] = ex2_f16x2(*reinterpret_cast<unsigned*>(&y1));
                pa[2] = ex2_f16x2(*reinterpret_cast<unsigned*>(&y2));
                pa[3] = ex2_f16x2(*reinterpret_cast<unsigned*>(&y3));
                float2 e0 = __half22float2(*reinterpret_cast<__half2*>(&pa[0]));
                float2 e1 = __half22float2(*reinterpret_cast<__half2*>(&pa[1]));
                float2 e2 = __half22float2(*reinterpret_cast<__half2*>(&pa[2]));
                float2 e3 = __half22float2(*reinterpret_cast<__half2*>(&pa[3]));
                psum0 += e0.x + e0.y + e2.x + e2.y;
                psum1 += e1.x + e1.y + e3.x + e3.y;
            }
            // V B-fragments: rows 16ks..16ks+15, all 64 d-cols (8 n-tiles)
            unsigned bv[8][2];
#pragma unroll
            for (int np = 0; np < 4; np++) {
                unsigned addr = v_base + (unsigned)(ks * 16 * VSH) * 2u +
                                (unsigned)(np * 16) * 2u;
                LDSM_X4_T(bv[2 * np][0], bv[2 * np][1],
                          bv[2 * np + 1][0], bv[2 * np + 1][1], addr);
            }
#pragma unroll
            for (int nt = 0; nt < 8; nt++)
                MMA_F16(oacc[nt], pa, bv[nt]);
        }
        psum0 += __shfl_xor_sync(0xffffffffu, psum0, 1);
        psum0 += __shfl_xor_sync(0xffffffffu, psum0, 2);
        psum1 += __shfl_xor_sync(0xffffffffu, psum1, 1);
        psum1 += __shfl_xor_sync(0xffffffffu, psum1, 2);
        l0 = l0 * c0 + psum0;
        l1 = l1 * c1 + psum1;
    }

    // ---- epilogue: normalize, zero fully-masked rows, add residual x ----
    any0 |= __shfl_xor_sync(0xffffffffu, any0, 1);
    any0 |= __shfl_xor_sync(0xffffffffu, any0, 2);
    any1 |= __shfl_xor_sync(0xffffffffu, any1, 1);
    any1 |= __shfl_xor_sync(0xffffffffu, any1, 2);
    {
        int r0 = wm + g, r1 = wm + g + 8;
        float inv0 = any0 ? (1.f / l0) : 0.f;
        float inv1 = any1 ? (1.f / l1) : 0.f;
#pragma unroll
        for (int nt = 0; nt < 8; nt++) {
            int col = h * DH + nt * 8 + 2 * t;
            size_t base0 = (size_t)(b * TT + q0 + r0) * DD + col;
            size_t base1 = (size_t)(b * TT + q0 + r1) * DD + col;
            float2 x0 = *reinterpret_cast<const float2*>(xin + base0);
            float2 x1 = *reinterpret_cast<const float2*>(xin + base1);
            float2 o0 = {oacc[nt][0] * inv0 + x0.x, oacc[nt][1] * inv0 + x0.y};
            float2 o1 = {oacc[nt][2] * inv1 + x1.x, oacc[nt][3] * inv1 + x1.y};
            *reinterpret_cast<float2*>(out + base0) = o0;
            *reinterpret_cast<float2*>(out + base1) = o1;
        }
    }
}

// ---------------------------------------------------------------------------
// Launch
// ---------------------------------------------------------------------------
extern "C" void kernel_launch(void* const* d_in, const int* in_sizes, int n_in,
                              void* d_out, int out_size) {
    const float* x     = (const float*)d_in[0];
    const int*   mask  = (const int*)  d_in[1];
    const float* Wq    = (const float*)d_in[2];
    const float* bq    = (const float*)d_in[3];
    const float* Wk    = (const float*)d_in[4];
    const float* bk    = (const float*)d_in[5];
    const float* Wv    = (const float*)d_in[6];
    const float* bv    = (const float*)d_in[7];
    const float* g_in  = (const float*)d_in[8];
    const float* b_in  = (const float*)d_in[9];
    const float* g1    = (const float*)d_in[10];
    const float* b1    = (const float*)d_in[11];
    const float* W_ff1 = (const float*)d_in[12];
    const float* b_ff1 = (const float*)d_in[13];
    const float* W_ff2 = (const float*)d_in[14];
    const float* b_ff2 = (const float*)d_in[15];
    const float* g2    = (const float*)d_in[16];
    const float* b2    = (const float*)d_in[17];
    float* out = (float*)d_out;

    __half *xn_h, *q_h, *k_h, *v_h, *h1n_h, *ff_h;
    __half *wq_h, *wk_h, *wv_h, *w1_h, *w2_h;
    float *res1, *res2;
    cudaGetSymbolAddress((void**)&xn_h,  g_xn_h);
    cudaGetSymbolAddress((void**)&q_h,   g_q_h);
    cudaGetSymbolAddress((void**)&k_h,   g_k_h);
    cudaGetSymbolAddress((void**)&v_h,   g_v_h);
    cudaGetSymbolAddress((void**)&h1n_h, g_h1n_h);
    cudaGetSymbolAddress((void**)&ff_h,  g_ff_h);
    cudaGetSymbolAddress((void**)&res1,  g_res1);
    cudaGetSymbolAddress((void**)&res2,  g_res2);
    cudaGetSymbolAddress((void**)&wq_h,  g_wq_h);
    cudaGetSymbolAddress((void**)&wk_h,  g_wk_h);
    cudaGetSymbolAddress((void**)&wv_h,  g_wv_h);
    cudaGetSymbolAddress((void**)&w1_h,  g_w1_h);
    cudaGetSymbolAddress((void**)&w2_h,  g_w2_h);

    cudaFuncSetAttribute(flash_tc_kernel,
                         cudaFuncAttributeMaxDynamicSharedMemorySize, FL_SMEM_BYTES);
    cudaFuncSetAttribute(h_gemm_kernel,
                         cudaFuncAttributeMaxDynamicSharedMemorySize, GEMM_SMEM);
    cudaFuncSetAttribute(h_gemm_qkv_kernel,
                         cudaFuncAttributeMaxDynamicSharedMemorySize, GEMM_SMEM);

    // 0. weight -> fp16 transposed copies w[n][k]
    {
        CvtTJobs jq;
        jq.in[0] = Wq; jq.in[1] = Wk; jq.in[2] = Wv;
        jq.out[0] = wq_h; jq.out[1] = wk_h; jq.out[2] = wv_h;
        cvt_half_T_kernel<<<dim3(DD / 32, DD / 32, 3), dim3(32, 8)>>>(jq, DD, DD);
        CvtTJobs j1;
        j1.in[0] = W_ff1; j1.in[1] = nullptr; j1.in[2] = nullptr;
        j1.out[0] = w1_h;
        cvt_half_T_kernel<<<dim3(FFN / 32, DD / 32, 1), dim3(32, 8)>>>(j1, DD, FFN);
        CvtTJobs j2;
        j2.in[0] = W_ff2; j2.in[1] = nullptr; j2.in[2] = nullptr;
        j2.out[0] = w2_h;
        cvt_half_T_kernel<<<dim3(DD / 32, FFN / 32, 1), dim3(32, 8)>>>(j2, FFN, DD);
    }

    // 1. pre-LN -> fp16
    ln1024_kernel<<<MROWS, 256>>>(x, g_in, b_in, nullptr, xn_h);

    // 2. QKV projections (fused grid.z; fp16 outputs)
    {
        QkvPtrs p;
        p.W[0] = wq_h; p.W[1] = wk_h; p.W[2] = wv_h;
        p.b[0] = bq;   p.b[1] = bk;   p.b[2] = bv;
        p.o[0] = q_h;  p.o[1] = k_h;  p.o[2] = v_h;
        h_gemm_qkv_kernel<<<dim3(DD / BN, MROWS / BM, 3), 128, GEMM_SMEM>>>(xn_h, p);
    }

    // 3. attention + residual(x) -> res1 (fp32)
    flash_tc_kernel<<<dim3(TT / 128, HH, BB), 256, FL_SMEM_BYTES>>>(
        q_h, k_h, v_h, mask, x, res1);

    // 4. LN -> fp16
    ln1024_kernel<<<MROWS, 256>>>(res1, g1, b1, nullptr, h1n_h);

    // 5. FF1 + relu -> fp16
    h_gemm_kernel<<<dim3(FFN / BN, MROWS / BM), 128, GEMM_SMEM>>>(
        MROWS, FFN, DD, h1n_h, w1_h, b_ff1, nullptr, ff_h, 1, 1);

    // 6. FF2 + bias + residual(res1) -> fp32
    h_gemm_kernel<<<dim3(DD / BN, MROWS / BM), 128, GEMM_SMEM>>>(
        MROWS, DD, FFN, ff_h, w2_h, b_ff2, res1, res2, 0, 0);

    // 7. final LN -> out (fp32)
    ln1024_kernel<<<MROWS, 256>>>(res2, g2, b2, out, nullptr);
}

// round 16
// speedup vs baseline: 1.2155x; 1.0247x over previous
#include <cuda_runtime.h>
#include <cuda_fp16.h>
#include <math.h>
#include <stdint.h>

// Problem constants
#define BB 2
#define TT 2048
#define DD 1024
#define HH 16
#define DH 64
#define FFN 4096
#define MROWS (BB*TT)          // 4096
#define LN_EPS 1e-3f

// FP16 GEMM tiling: 128x128x32 block, 128 threads (4 warps), warp tile 64x64
#define BM 128
#define BN 128
#define BKK 32                  // k-halves per stage
#define ASH 40                  // A smem row stride (halves)
#define BSH 40
#define STAGE_HALVES (BM*ASH + BN*BSH)      // 10240
#define GEMM_SMEM (2*STAGE_HALVES*2)        // 40960 bytes

// Flash tiling (fp16, FA2-style register pipeline)
#define QSH 72                  // [q][d] halves
#define KSH 72                  // [t][d] halves
#define VSH 72                  // [t][d] halves
#define FL_SMEM_BYTES ((128*QSH + 2*64*KSH + 2*64*VSH)*2)   // 55296

#define NMW (TT/64)             // 32 mask words per row

// ---------------------------------------------------------------------------
// Scratch (device globals; no allocation allowed)
// ---------------------------------------------------------------------------
__device__ __half g_xn_h [MROWS*DD];
__device__ __half g_q_h  [MROWS*DD];
__device__ __half g_k_h  [MROWS*DD];
__device__ __half g_v_h  [MROWS*DD];
__device__ __half g_h1n_h[MROWS*DD];
__device__ __half g_ff_h [MROWS*FFN];
__device__ float  g_res1 [MROWS*DD];
__device__ float  g_res2 [MROWS*DD];
__device__ unsigned long long g_pm[BB*TT*NMW];   // packed mask bits (1 MB)
// fp16 TRANSPOSED weight copies w[n][k]
__device__ __half g_wq_h[DD*DD];
__device__ __half g_wk_h[DD*DD];
__device__ __half g_wv_h[DD*DD];
__device__ __half g_w1_h[FFN*DD];
__device__ __half g_w2_h[DD*FFN];

// ---------------------------------------------------------------------------
// Helpers
// ---------------------------------------------------------------------------
__device__ __forceinline__ void cp16(void* dst, const void* src) {
    unsigned s = (unsigned)__cvta_generic_to_shared(dst);
    asm volatile("cp.async.cg.shared.global [%0], [%1], 16;" :: "r"(s), "l"(src));
}

__device__ __forceinline__ unsigned smem_addr(const void* p) {
    return (unsigned)__cvta_generic_to_shared(p);
}

#define MMA_F16(c, a, b) \
    asm volatile("mma.sync.aligned.m16n8k16.row.col.f32.f16.f16.f32 " \
        "{%0,%1,%2,%3}, {%4,%5,%6,%7}, {%8,%9}, {%0,%1,%2,%3};" \
        : "+f"((c)[0]), "+f"((c)[1]), "+f"((c)[2]), "+f"((c)[3]) \
        : "r"((a)[0]), "r"((a)[1]), "r"((a)[2]), "r"((a)[3]), \
          "r"((b)[0]), "r"((b)[1]))

#define LDSM_X4(r0, r1, r2, r3, addr) \
    asm volatile("ldmatrix.sync.aligned.m8n8.x4.shared.b16 {%0,%1,%2,%3}, [%4];" \
        : "=r"(r0), "=r"(r1), "=r"(r2), "=r"(r3) : "r"(addr))

#define LDSM_X4_T(r0, r1, r2, r3, addr) \
    asm volatile("ldmatrix.sync.aligned.m8n8.x4.trans.shared.b16 {%0,%1,%2,%3}, [%4];" \
        : "=r"(r0), "=r"(r1), "=r"(r2), "=r"(r3) : "r"(addr))

// two fp16 exponentials (base-2) in ONE MUFU op
__device__ __forceinline__ unsigned ex2_f16x2(unsigned y) {
    unsigned r;
    asm("ex2.approx.f16x2 %0, %1;" : "=r"(r) : "r"(y));
    return r;
}

// ---------------------------------------------------------------------------
// Mask pack: mask[b][t][col] (int 0/1) -> pm[b][t][w] bit per col (64/word)
// ---------------------------------------------------------------------------
__global__ void pack_mask_kernel(const int* __restrict__ mask,
                                 unsigned long long* __restrict__ pm) {
    int idx = blockIdx.x * 256 + threadIdx.x;     // 0 .. BB*TT*NMW-1
    const int* src = mask + (size_t)idx * 64;
    unsigned long long bits = 0;
#pragma unroll
    for (int i = 0; i < 64; i += 4) {
        int4 v = *reinterpret_cast<const int4*>(src + i);
        unsigned nib = (v.x ? 1u : 0u) | (v.y ? 2u : 0u) |
                       (v.z ? 4u : 0u) | (v.w ? 8u : 0u);
        bits |= (unsigned long long)nib << i;
    }
    pm[idx] = bits;
}

// ---------------------------------------------------------------------------
// Weight -> fp16 (rn) + transpose: in[K][N] fp32 -> out[N][K] half
// ---------------------------------------------------------------------------
struct CvtTJobs {
    const float* in[3];
    __half* out[3];
};

__global__ void cvt_half_T_kernel(CvtTJobs j, int K, int N) {
    __shared__ float tile[32][33];
    int z = blockIdx.z;
    if (!j.in[z]) return;
    const float* in = j.in[z];
    __half* outp = j.out[z];
    int n0 = blockIdx.x * 32, k0 = blockIdx.y * 32;
    int tx = threadIdx.x, ty = threadIdx.y;   // 32 x 8
#pragma unroll
    for (int i = 0; i < 4; i++)
        tile[ty + 8 * i][tx] = in[(size_t)(k0 + ty + 8 * i) * N + n0 + tx];
    __syncthreads();
#pragma unroll
    for (int i = 0; i < 4; i++)
        outp[(size_t)(n0 + ty + 8 * i) * K + k0 + tx] =
            __float2half_rn(tile[tx][ty + 8 * i]);
}

// ---------------------------------------------------------------------------
// LayerNorm over last dim (D=1024); writes fp32 OR fp16 output
// ---------------------------------------------------------------------------
__device__ __forceinline__ float block_reduce_sum_256(float v, float* red) {
    __syncthreads();
#pragma unroll
    for (int o = 16; o > 0; o >>= 1) v += __shfl_xor_sync(0xffffffffu, v, o);
    int lane = threadIdx.x & 31, wid = threadIdx.x >> 5;
    if (lane == 0) red[wid] = v;
    __syncthreads();
    if (wid == 0) {
        v = (lane < 8) ? red[lane] : 0.f;
#pragma unroll
        for (int o = 4; o > 0; o >>= 1) v += __shfl_xor_sync(0xffffffffu, v, o);
        if (lane == 0) red[0] = v;
    }
    __syncthreads();
    return red[0];
}

__global__ void ln1024_kernel(const float* __restrict__ x,
                              const float* __restrict__ gamma,
                              const float* __restrict__ beta,
                              float* __restrict__ outf,
                              __half* __restrict__ outh) {
    __shared__ float red[8];
    int row = blockIdx.x;
    int t = threadIdx.x;
    const float4 v = reinterpret_cast<const float4*>(x + (size_t)row * DD)[t];

    float s = v.x + v.y + v.z + v.w;
    float mu = block_reduce_sum_256(s, red) * (1.0f / DD);

    float dx = v.x - mu, dy = v.y - mu, dz = v.z - mu, dw = v.w - mu;
    float q = dx*dx + dy*dy + dz*dz + dw*dw;
    float var = block_reduce_sum_256(q, red) * (1.0f / DD);
    float r = rsqrtf(var + LN_EPS);

    const float4 gg = reinterpret_cast<const float4*>(gamma)[t];
    const float4 bb = reinterpret_cast<const float4*>(beta)[t];
    float o0 = dx * r * gg.x + bb.x;
    float o1 = dy * r * gg.y + bb.y;
    float o2 = dz * r * gg.z + bb.z;
    float o3 = dw * r * gg.w + bb.w;
    if (outh) {
        __half2 h0 = __floats2half2_rn(o0, o1);
        __half2 h1 = __floats2half2_rn(o2, o3);
        reinterpret_cast<__half2*>(outh + (size_t)row * DD)[2 * t] = h0;
        reinterpret_cast<__half2*>(outh + (size_t)row * DD)[2 * t + 1] = h1;
    } else {
        float4 o = {o0, o1, o2, o3};
        reinterpret_cast<float4*>(outf + (size_t)row * DD)[t] = o;
    }
}

// ---------------------------------------------------------------------------
// FP16 tensor-core GEMM (unchanged)
// ---------------------------------------------------------------------------
__device__ __forceinline__ void gemm_prefetch(const __half* __restrict__ A,
                                              const __half* __restrict__ Bt,
                                              int K, int bm0, int bn0,
                                              int kt, __half* As, __half* Bs,
                                              int tid) {
#pragma unroll
    for (int i = 0; i < 4; i++) {
        int lin = tid + i * 128;               // 0..511
        int row = lin >> 2, c8 = (lin & 3) << 3;
        cp16(As + row * ASH + c8,
             A + (size_t)(bm0 + row) * K + (size_t)kt * BKK + c8);
    }
#pragma unroll
    for (int i = 0; i < 4; i++) {
        int lin = tid + i * 128;
        int row = lin >> 2, c8 = (lin & 3) << 3;
        cp16(Bs + row * BSH + c8,
             Bt + (size_t)(bn0 + row) * K + (size_t)kt * BKK + c8);
    }
}

__device__ __forceinline__ void gemm_core(int M, int N, int K,
    const __half* __restrict__ A, const __half* __restrict__ Bt,
    const float* __restrict__ bias, const float* __restrict__ resid,
    void* __restrict__ Cp, int relu, int out_half) {
    extern __shared__ __half smh[];
    const int tid = threadIdx.x;
    const int warp = tid >> 5, lane = tid & 31;
    const int g = lane >> 2, t = lane & 3;
    const int wm0 = (warp & 1) << 6;
    const int wn0 = (warp >> 1) << 6;
    const int bm0 = blockIdx.y * BM, bn0 = blockIdx.x * BN;

    const int sub = lane >> 3, lr = lane & 7;
    const int a_roff = ((sub & 1) << 3) + lr;
    const int a_coff = (sub >> 1) << 3;
    const int b_roff = ((sub >> 1) << 3) + lr;
    const int b_coff = (sub & 1) << 3;

    float acc[4][8][4];
#pragma unroll
    for (int i = 0; i < 4; i++)
#pragma unroll
        for (int j = 0; j < 8; j++)
#pragma unroll
            for (int r = 0; r < 4; r++) acc[i][j][r] = 0.f;

    const int nkt = K / BKK;
    gemm_prefetch(A, Bt, K, bm0, bn0, 0, smh, smh + BM * ASH, tid);
    asm volatile("cp.async.commit_group;");

    int buf = 0;
    for (int kt = 0; kt < nkt; kt++) {
        asm volatile("cp.async.wait_group 0;");
        __syncthreads();
        if (kt + 1 < nkt) {
            __half* As_n = smh + (buf ^ 1) * STAGE_HALVES;
            gemm_prefetch(A, Bt, K, bm0, bn0, kt + 1, As_n,
                          As_n + BM * ASH, tid);
            asm volatile("cp.async.commit_group;");
        }
        const __half* As = smh + buf * STAGE_HALVES;
        const __half* Bs = As + BM * ASH;
        const unsigned a_base = smem_addr(As) +
            ((unsigned)(wm0 + a_roff) * ASH + a_coff) * 2u;
        const unsigned b_base = smem_addr(Bs) +
            ((unsigned)(wn0 + b_roff) * BSH + b_coff) * 2u;
#pragma unroll
        for (int ks = 0; ks < 2; ks++) {
            const unsigned kkb = (unsigned)(ks * 16) * 2u;
            unsigned av[4][4], bv[8][2];
#pragma unroll
            for (int mt = 0; mt < 4; mt++) {
                unsigned addr = a_base + (unsigned)(mt * 16 * ASH) * 2u + kkb;
                LDSM_X4(av[mt][0], av[mt][1], av[mt][2], av[mt][3], addr);
            }
#pragma unroll
            for (int np = 0; np < 4; np++) {
                unsigned addr = b_base + (unsigned)(np * 16 * BSH) * 2u + kkb;
                LDSM_X4(bv[2 * np][0], bv[2 * np][1],
                        bv[2 * np + 1][0], bv[2 * np + 1][1], addr);
            }
#pragma unroll
            for (int mt = 0; mt < 4; mt++)
#pragma unroll
                for (int nt = 0; nt < 8; nt++)
                    MMA_F16(acc[mt][nt], av[mt], bv[nt]);
        }
        buf ^= 1;
    }

#pragma unroll
    for (int mt = 0; mt < 4; mt++) {
#pragma unroll
        for (int nt = 0; nt < 8; nt++) {
            int row = bm0 + wm0 + mt * 16 + g;
            int col = bn0 + wn0 + nt * 8 + t * 2;
            float bb0 = bias[col], bb1 = bias[col + 1];
            float o0 = acc[mt][nt][0] + bb0;
            float o1 = acc[mt][nt][1] + bb1;
            float o2 = acc[mt][nt][2] + bb0;
            float o3 = acc[mt][nt][3] + bb1;
            if (relu) {
                o0 = fmaxf(o0, 0.f); o1 = fmaxf(o1, 0.f);
                o2 = fmaxf(o2, 0.f); o3 = fmaxf(o3, 0.f);
            }
            if (resid) {
                float2 r0 = *reinterpret_cast<const float2*>(
                    resid + (size_t)row * N + col);
                float2 r1 = *reinterpret_cast<const float2*>(
                    resid + (size_t)(row + 8) * N + col);
                o0 += r0.x; o1 += r0.y; o2 += r1.x; o3 += r1.y;
            }
            if (out_half) {
                __half* Ch = (__half*)Cp;
                *reinterpret_cast<__half2*>(Ch + (size_t)row * N + col) =
                    __floats2half2_rn(o0, o1);
                *reinterpret_cast<__half2*>(Ch + (size_t)(row + 8) * N + col) =
                    __floats2half2_rn(o2, o3);
            } else {
                float* Cf = (float*)Cp;
                float2 s0 = {o0, o1}, s1 = {o2, o3};
                *reinterpret_cast<float2*>(Cf + (size_t)row * N + col) = s0;
                *reinterpret_cast<float2*>(Cf + (size_t)(row + 8) * N + col) = s1;
            }
        }
    }
}

__global__ __launch_bounds__(128, 2)
void h_gemm_kernel(int M, int N, int K, const __half* __restrict__ A,
                   const __half* __restrict__ Bt,
                   const float* __restrict__ bias,
                   const float* __restrict__ resid,
                   void* __restrict__ C, int relu, int out_half) {
    gemm_core(M, N, K, A, Bt, bias, resid, C, relu, out_half);
}

struct QkvPtrs {
    const __half* W[3];
    const float* b[3];
    __half* o[3];
};

__global__ __launch_bounds__(128, 2)
void h_gemm_qkv_kernel(const __half* __restrict__ A, QkvPtrs p) {
    int z = blockIdx.z;
    gemm_core(MROWS, DD, DD, A, p.W[z], p.b[z], nullptr, p.o[z], 0, 1);
}

// ---------------------------------------------------------------------------
// Flash attention, FA2-style register pipeline + packed bitmask.
// CTA = (b, h, 128 q-rows). 8 warps; warp = 16 q-rows x full 64 k-cols.
// ---------------------------------------------------------------------------
__device__ __forceinline__ void fl_prefetch_kv(const __half* __restrict__ Kp,
                                               const __half* __restrict__ Vp,
                                               __half* Ks, __half* Vs, int tid) {
#pragma unroll
    for (int i = 0; i < 2; i++) {
        int lin = tid + i * 256;           // 0..511
        int row = lin >> 3, c8 = (lin & 7) << 3;
        cp16(Ks + row * KSH + c8, Kp + (size_t)row * DD + c8);
        cp16(Vs + row * VSH + c8, Vp + (size_t)row * DD + c8);
    }
}

__global__ __launch_bounds__(256, 2)
void flash_tc_kernel(const __half* __restrict__ Q,
                     const __half* __restrict__ Kg,
                     const __half* __restrict__ Vg,
                     const unsigned long long* __restrict__ pm,
                     const float* __restrict__ xin,
                     float* __restrict__ out) {
    extern __shared__ char smraw[];
    __half* Qs = (__half*)smraw;                       // [128][QSH]
    __half* Ks = Qs + 128 * QSH;                       // 2x [64][KSH]
    __half* Vs = Ks + 2 * 64 * KSH;                    // 2x [64][VSH]

    const int tid = threadIdx.x;
    const int warp = tid >> 5, lane = tid & 31;
    const int g = lane >> 2, t = lane & 3;
    const int wm = warp << 4;           // warp q-row base: 0..112
    const int qt = blockIdx.x, h = blockIdx.y, b = blockIdx.z;
    const int q0 = qt * 128;

    const int sub = lane >> 3, lr = lane & 7;
    const int a_roff = ((sub & 1) << 3) + lr;
    const int a_coff = (sub >> 1) << 3;
    const int b_roff = ((sub >> 1) << 3) + lr;
    const int b_coff = (sub & 1) << 3;
    const int vt_roff = ((sub & 1) << 3) + lr;
    const int vt_coff = (sub >> 1) << 3;

    const __half* Qgp = Q + ((size_t)(b * TT + q0) * DD + h * DH);
    // packed-mask word pointers for rows wm+g and wm+g+8
    const unsigned long long* pm0 = pm + ((size_t)(b * TT + q0 + wm + g)) * NMW;
    const unsigned long long* pm1 = pm0 + 8 * NMW;

    // prologue: prefetch Q (128 rows) + K/V tile 0
#pragma unroll
    for (int i = 0; i < 4; i++) {
        int lin = tid + i * 256;           // 0..1023
        int row = lin >> 3, c8 = (lin & 7) << 3;
        cp16(Qs + row * QSH + c8, Qgp + (size_t)row * DD + c8);
    }
    fl_prefetch_kv(Kg + ((size_t)(b * TT) * DD + h * DH),
                   Vg + ((size_t)(b * TT) * DD + h * DH), Ks, Vs, tid);
    asm volatile("cp.async.commit_group;");

    // register state
    float m0 = -INFINITY, m1 = -INFINITY, l0 = 0.f, l1 = 0.f;
    int any0 = 0, any1 = 0;
    float oacc[8][4];
#pragma unroll
    for (int nt = 0; nt < 8; nt++)
#pragma unroll
        for (int r = 0; r < 4; r++) oacc[nt][r] = 0.f;

    const unsigned q_base = smem_addr(Qs) +
        ((unsigned)(wm + a_roff) * QSH + a_coff) * 2u;
    const float LOG2E = 1.4426950408889634f;

    for (int kt = 0; kt < TT / 64; kt++) {
        const int bufi = kt & 1;
        const __half* Kb = Ks + bufi * 64 * KSH;
        const __half* Vb = Vs + bufi * 64 * VSH;

        asm volatile("cp.async.wait_group 0;");
        __syncthreads();
        if (kt + 1 < TT / 64) {
            const int k1 = (kt + 1) * 64;
            fl_prefetch_kv(Kg + ((size_t)(b * TT + k1) * DD + h * DH),
                           Vg + ((size_t)(b * TT + k1) * DD + h * DH),
                           Ks + (bufi ^ 1) * 64 * KSH,
                           Vs + (bufi ^ 1) * 64 * VSH, tid);
            asm volatile("cp.async.commit_group;");
        }

        // packed mask words for this tile (8B per row; quad-broadcast)
        unsigned long long w0 = pm0[kt], w1 = pm1[kt];
        any0 |= (w0 != 0ull);
        any1 |= (w1 != 0ull);
        // extract this thread's 16 bits: col 8nt+2t (+1)
        unsigned mbits0 = 0, mbits1 = 0;
#pragma unroll
        for (int nt = 0; nt < 8; nt++) {
            mbits0 |= (unsigned)((w0 >> (8 * nt + 2 * t)) & 3ull) << (2 * nt);
            mbits1 |= (unsigned)((w1 >> (8 * nt + 2 * t)) & 3ull) << (2 * nt);
        }

        // ---- S = Q K^T: warp computes 16q x 64k ----
        float sacc[8][4];
#pragma unroll
        for (int nt = 0; nt < 8; nt++)
#pragma unroll
            for (int r = 0; r < 4; r++) sacc[nt][r] = 0.f;
        const unsigned kb_base = smem_addr(Kb) +
            ((unsigned)b_roff * KSH + b_coff) * 2u;
#pragma unroll
        for (int ks = 0; ks < 4; ks++) {
            const unsigned kkb = (unsigned)(ks * 16) * 2u;
            unsigned a[4], bv[8][2];
            LDSM_X4(a[0], a[1], a[2], a[3], q_base + kkb);
#pragma unroll
            for (int np = 0; np < 4; np++) {
                unsigned addr = kb_base + (unsigned)(np * 16 * KSH) * 2u + kkb;
                LDSM_X4(bv[2 * np][0], bv[2 * np][1],
                        bv[2 * np + 1][0], bv[2 * np + 1][1], addr);
            }
#pragma unroll
            for (int nt = 0; nt < 8; nt++)
                MMA_F16(sacc[nt], a, bv[nt]);
        }

        // ---- scale + mask + row max (registers + quad shfl) ----
        float mx0 = -INFINITY, mx1 = -INFINITY;
#pragma unroll
        for (int nt = 0; nt < 8; nt++) {
            float b0 = ((mbits0 >> (2 * nt)) & 1) ? 0.f : -1e9f;
            float b1 = ((mbits0 >> (2 * nt + 1)) & 1) ? 0.f : -1e9f;
            float b2 = ((mbits1 >> (2 * nt)) & 1) ? 0.f : -1e9f;
            float b3 = ((mbits1 >> (2 * nt + 1)) & 1) ? 0.f : -1e9f;
            sacc[nt][0] = sacc[nt][0] * 0.125f + b0;
            sacc[nt][1] = sacc[nt][1] * 0.125f + b1;
            sacc[nt][2] = sacc[nt][2] * 0.125f + b2;
            sacc[nt][3] = sacc[nt][3] * 0.125f + b3;
            mx0 = fmaxf(mx0, fmaxf(sacc[nt][0], sacc[nt][1]));
            mx1 = fmaxf(mx1, fmaxf(sacc[nt][2], sacc[nt][3]));
        }
        mx0 = fmaxf(mx0, __shfl_xor_sync(0xffffffffu, mx0, 1));
        mx0 = fmaxf(mx0, __shfl_xor_sync(0xffffffffu, mx0, 2));
        mx1 = fmaxf(mx1, __shfl_xor_sync(0xffffffffu, mx1, 1));
        mx1 = fmaxf(mx1, __shfl_xor_sync(0xffffffffu, mx1, 2));
        float mnew0 = fmaxf(m0, mx0);
        float mnew1 = fmaxf(m1, mx1);
        float c0 = __expf(m0 - mnew0);   // 0 on first tile
        float c1 = __expf(m1 - mnew1);
        m0 = mnew0; m1 = mnew1;

        // rescale O before accumulating this tile
#pragma unroll
        for (int nt = 0; nt < 8; nt++) {
            oacc[nt][0] *= c0; oacc[nt][1] *= c0;
            oacc[nt][2] *= c1; oacc[nt][3] *= c1;
        }

        // ---- exp (f16x2) fused with PV mma; P frags straight from sacc ----
        float psum0 = 0.f, psum1 = 0.f;
        const unsigned v_base = smem_addr(Vb) +
            ((unsigned)vt_roff * VSH + vt_coff) * 2u;
#pragma unroll
        for (int ks = 0; ks < 4; ks++) {
            unsigned pa[4];
            {
                float* s0 = sacc[2 * ks];
                float* s1 = sacc[2 * ks + 1];
                __half2 y0 = __floats2half2_rn((s0[0] - mnew0) * LOG2E,
                                               (s0[1] - mnew0) * LOG2E);
                __half2 y1 = __floats2half2_rn((s0[2] - mnew1) * LOG2E,
                                               (s0[3] - mnew1) * LOG2E);
                __half2 y2 = __floats2half2_rn((s1[0] - mnew0) * LOG2E,
                                               (s1[1] - mnew0) * LOG2E);
                __half2 y3 = __floats2half2_rn((s1[2] - mnew1) * LOG2E,
                                               (s1[3] - mnew1) * LOG2E);
                pa[0] = ex2_f16x2(*reinterpret_cast<unsigned*>(&y0));
                pa[1] = ex2_f16x2(*reinterpret_cast<unsigned*>(&y1));
                pa[2] = ex2_f16x2(*reinterpret_cast<unsigned*>(&y2));
                pa[3] = ex2_f16x2(*reinterpret_cast<unsigned*>(&y3));
                float2 e0 = __half22float2(*reinterpret_cast<__half2*>(&pa[0]));
                float2 e1 = __half22float2(*reinterpret_cast<__half2*>(&pa[1]));
                float2 e2 = __half22float2(*reinterpret_cast<__half2*>(&pa[2]));
                float2 e3 = __half22float2(*reinterpret_cast<__half2*>(&pa[3]));
                psum0 += e0.x + e0.y + e2.x + e2.y;
                psum1 += e1.x + e1.y + e3.x + e3.y;
            }
            unsigned bv[8][2];
#pragma unroll
            for (int np = 0; np < 4; np++) {
                unsigned addr = v_base + (unsigned)(ks * 16 * VSH) * 2u +
                                (unsigned)(np * 16) * 2u;
                LDSM_X4_T(bv[2 * np][0], bv[2 * np][1],
                          bv[2 * np + 1][0], bv[2 * np + 1][1], addr);
            }
#pragma unroll
            for (int nt = 0; nt < 8; nt++)
                MMA_F16(oacc[nt], pa, bv[nt]);
        }
        psum0 += __shfl_xor_sync(0xffffffffu, psum0, 1);
        psum0 += __shfl_xor_sync(0xffffffffu, psum0, 2);
        psum1 += __shfl_xor_sync(0xffffffffu, psum1, 1);
        psum1 += __shfl_xor_sync(0xffffffffu, psum1, 2);
        l0 = l0 * c0 + psum0;
        l1 = l1 * c1 + psum1;
    }

    // ---- epilogue: normalize, zero fully-masked rows, add residual x ----
    {
        int r0 = wm + g, r1 = wm + g + 8;
        float inv0 = any0 ? (1.f / l0) : 0.f;
        float inv1 = any1 ? (1.f / l1) : 0.f;
#pragma unroll
        for (int nt = 0; nt < 8; nt++) {
            int col = h * DH + nt * 8 + 2 * t;
            size_t base0 = (size_t)(b * TT + q0 + r0) * DD + col;
            size_t base1 = (size_t)(b * TT + q0 + r1) * DD + col;
            float2 x0 = *reinterpret_cast<const float2*>(xin + base0);
            float2 x1 = *reinterpret_cast<const float2*>(xin + base1);
            float2 o0 = {oacc[nt][0] * inv0 + x0.x, oacc[nt][1] * inv0 + x0.y};
            float2 o1 = {oacc[nt][2] * inv1 + x1.x, oacc[nt][3] * inv1 + x1.y};
            *reinterpret_cast<float2*>(out + base0) = o0;
            *reinterpret_cast<float2*>(out + base1) = o1;
        }
    }
}

// ---------------------------------------------------------------------------
// Launch
// ---------------------------------------------------------------------------
extern "C" void kernel_launch(void* const* d_in, const int* in_sizes, int n_in,
                              void* d_out, int out_size) {
    const float* x     = (const float*)d_in[0];
    const int*   mask  = (const int*)  d_in[1];
    const float* Wq    = (const float*)d_in[2];
    const float* bq    = (const float*)d_in[3];
    const float* Wk    = (const float*)d_in[4];
    const float* bk    = (const float*)d_in[5];
    const float* Wv    = (const float*)d_in[6];
    const float* bv    = (const float*)d_in[7];
    const float* g_in  = (const float*)d_in[8];
    const float* b_in  = (const float*)d_in[9];
    const float* g1    = (const float*)d_in[10];
    const float* b1    = (const float*)d_in[11];
    const float* W_ff1 = (const float*)d_in[12];
    const float* b_ff1 = (const float*)d_in[13];
    const float* W_ff2 = (const float*)d_in[14];
    const float* b_ff2 = (const float*)d_in[15];
    const float* g2    = (const float*)d_in[16];
    const float* b2    = (const float*)d_in[17];
    float* out = (float*)d_out;

    __half *xn_h, *q_h, *k_h, *v_h, *h1n_h, *ff_h;
    __half *wq_h, *wk_h, *wv_h, *w1_h, *w2_h;
    float *res1, *res2;
    unsigned long long* pm;
    cudaGetSymbolAddress((void**)&xn_h,  g_xn_h);
    cudaGetSymbolAddress((void**)&q_h,   g_q_h);
    cudaGetSymbolAddress((void**)&k_h,   g_k_h);
    cudaGetSymbolAddress((void**)&v_h,   g_v_h);
    cudaGetSymbolAddress((void**)&h1n_h, g_h1n_h);
    cudaGetSymbolAddress((void**)&ff_h,  g_ff_h);
    cudaGetSymbolAddress((void**)&res1,  g_res1);
    cudaGetSymbolAddress((void**)&res2,  g_res2);
    cudaGetSymbolAddress((void**)&pm,    g_pm);
    cudaGetSymbolAddress((void**)&wq_h,  g_wq_h);
    cudaGetSymbolAddress((void**)&wk_h,  g_wk_h);
    cudaGetSymbolAddress((void**)&wv_h,  g_wv_h);
    cudaGetSymbolAddress((void**)&w1_h,  g_w1_h);
    cudaGetSymbolAddress((void**)&w2_h,  g_w2_h);

    cudaFuncSetAttribute(flash_tc_kernel,
                         cudaFuncAttributeMaxDynamicSharedMemorySize, FL_SMEM_BYTES);
    cudaFuncSetAttribute(h_gemm_kernel,
                         cudaFuncAttributeMaxDynamicSharedMemorySize, GEMM_SMEM);
    cudaFuncSetAttribute(h_gemm_qkv_kernel,
                         cudaFuncAttributeMaxDynamicSharedMemorySize, GEMM_SMEM);

    // 0a. pack mask into bitmask (1 MB, L2-resident)
    pack_mask_kernel<<<BB * TT * NMW / 256, 256>>>(mask, pm);

    // 0b. weight -> fp16 transposed copies w[n][k]
    {
        CvtTJobs jq;
        jq.in[0] = Wq; jq.in[1] = Wk; jq.in[2] = Wv;
        jq.out[0] = wq_h; jq.out[1] = wk_h; jq.out[2] = wv_h;
        cvt_half_T_kernel<<<dim3(DD / 32, DD / 32, 3), dim3(32, 8)>>>(jq, DD, DD);
        CvtTJobs j1;
        j1.in[0] = W_ff1; j1.in[1] = nullptr; j1.in[2] = nullptr;
        j1.out[0] = w1_h;
        cvt_half_T_kernel<<<dim3(FFN / 32, DD / 32, 1), dim3(32, 8)>>>(j1, DD, FFN);
        CvtTJobs j2;
        j2.in[0] = W_ff2; j2.in[1] = nullptr; j2.in[2] = nullptr;
        j2.out[0] = w2_h;
        cvt_half_T_kernel<<<dim3(DD / 32, FFN / 32, 1), dim3(32, 8)>>>(j2, FFN, DD);
    }

    // 1. pre-LN -> fp16
    ln1024_kernel<<<MROWS, 256>>>(x, g_in, b_in, nullptr, xn_h);

    // 2. QKV projections (fused grid.z; fp16 outputs)
    {
        QkvPtrs p;
        p.W[0] = wq_h; p.W[1] = wk_h; p.W[2] = wv_h;
        p.b[0] = bq;   p.b[1] = bk;   p.b[2] = bv;
        p.o[0] = q_h;  p.o[1] = k_h;  p.o[2] = v_h;
        h_gemm_qkv_kernel<<<dim3(DD / BN, MROWS / BM, 3), 128, GEMM_SMEM>>>(xn_h, p);
    }

    // 3. attention + residual(x) -> res1 (fp32)
    flash_tc_kernel<<<dim3(TT / 128, HH, BB), 256, FL_SMEM_BYTES>>>(
        q_h, k_h, v_h, pm, x, res1);

    // 4. LN -> fp16
    ln1024_kernel<<<MROWS, 256>>>(res1, g1, b1, nullptr, h1n_h);

    // 5. FF1 + relu -> fp16
    h_gemm_kernel<<<dim3(FFN / BN, MROWS / BM), 128, GEMM_SMEM>>>(
        MROWS, FFN, DD, h1n_h, w1_h, b_ff1, nullptr, ff_h, 1, 1);

    // 6. FF2 + bias + residual(res1) -> fp32
    h_gemm_kernel<<<dim3(DD / BN, MROWS / BM), 128, GEMM_SMEM>>>(
        MROWS, DD, FFN, ff_h, w2_h, b_ff2, res1, res2, 0, 0);

    // 7. final LN -> out (fp32)
    ln1024_kernel<<<MROWS, 256>>>(res2, g2, b2, out, nullptr);
}